// round 1
// baseline (speedup 1.0000x reference)
#include <cuda_runtime.h>

// DistMaps: out[b,g,r,c] = tanh(2*sqrt(min_p d2)) over 24 clicks per (b,g) group,
// d2 = ((r-pr)/5)^2 + ((c-pc)/5)^2, invalid clicks (max(pr,pc)<0) -> 1e6.
// x input (d_in[0]) is shape-only; output depends only on coords (d_in[1]).

namespace {

constexpr int   H         = 512;
constexpr int   W         = 512;
constexpr int   P         = 24;      // clicks per group
constexpr float INV_SCALE = 0.2f;    // 1 / (NORM_RADIUS * SPATIAL_SCALE)
// For d2 >= 41: x = 2*sqrt(d2) >= 12.8, 1-tanh(x) ~ 1.5e-11 << 2^-25,
// so tanhf rounds to exactly 1.0f in both reference and kernel. Safe cull bound.
constexpr float CULL_D2   = 41.0f;

__device__ __forceinline__ float tanh_2sqrt(float q) {
    // tanh(2*sqrt(q)) = (1 - e^{-4s}) / (1 + e^{-4s}), s = sqrt(q)
    float s = sqrtf(q);
    float u = __expf(-4.0f * s);
    return __fdividef(1.0f - u, 1.0f + u);
}

__global__ __launch_bounds__(128, 8) void distmaps_kernel(
    const float* __restrict__ coords,   // [B, 48, 3] (row, col, _)
    float*       __restrict__ out)      // [B, 2, H, W]
{
    __shared__ float s_pcs[P];   // scaled click col
    __shared__ float s_dr2[P];   // scaled row-distance^2 for this row
    __shared__ int   s_n;

    const int row = blockIdx.x;      // 0..H-1
    const int bg  = blockIdx.y;      // b*2 + g, 0..2B-1
    const int tid = threadIdx.x;     // 0..127, each thread owns 4 columns

    // Warp 0: compute per-click row terms, cull clicks with dr2 >= CULL_D2,
    // compact survivors into shared memory.
    if (tid < 32) {
        bool  near = false;
        float pcs = 0.0f, dr2 = 0.0f;
        if (tid < P) {
            // coords[b, g*24 + tid, :] -> flat ((bg)*24 + tid)*3
            const float* cp = coords + (size_t)(bg * P + tid) * 3;
            float pr = cp[0];
            float pc = cp[1];
            bool valid = fmaxf(pr, pc) >= 0.0f;   // invalid iff both coords < 0
            float drs = ((float)row - pr) * INV_SCALE;
            dr2 = drs * drs;
            pcs = pc * INV_SCALE;
            near = valid && (dr2 < CULL_D2);
        }
        unsigned mask = __ballot_sync(0xffffffffu, near);
        if (near) {
            int pos = __popc(mask & ((1u << tid) - 1u));
            s_pcs[pos] = pcs;
            s_dr2[pos] = dr2;
        }
        if (tid == 0) s_n = __popc(mask);
    }
    __syncthreads();

    const int n = s_n;

    const float a0 = (float)(tid * 4 + 0) * INV_SCALE;
    const float a1 = (float)(tid * 4 + 1) * INV_SCALE;
    const float a2 = (float)(tid * 4 + 2) * INV_SCALE;
    const float a3 = (float)(tid * 4 + 3) * INV_SCALE;

    // Clamp min at CULL_D2: any true min >= 41 produces exactly 1.0f anyway.
    float q0 = CULL_D2, q1 = CULL_D2, q2 = CULL_D2, q3 = CULL_D2;

    for (int p = 0; p < n; ++p) {
        float pcs = s_pcs[p];    // LDS broadcast
        float dr2 = s_dr2[p];
        float d;
        d = a0 - pcs; q0 = fminf(q0, fmaf(d, d, dr2));
        d = a1 - pcs; q1 = fminf(q1, fmaf(d, d, dr2));
        d = a2 - pcs; q2 = fminf(q2, fmaf(d, d, dr2));
        d = a3 - pcs; q3 = fminf(q3, fmaf(d, d, dr2));
    }

    float4 r;
    bool sat = (q0 >= CULL_D2) && (q1 >= CULL_D2) &&
               (q2 >= CULL_D2) && (q3 >= CULL_D2);
    if (__all_sync(0xffffffffu, sat)) {
        // Whole warp saturated: skip sqrt/exp/div entirely.
        r = make_float4(1.0f, 1.0f, 1.0f, 1.0f);
    } else {
        r.x = tanh_2sqrt(q0);
        r.y = tanh_2sqrt(q1);
        r.z = tanh_2sqrt(q2);
        r.w = tanh_2sqrt(q3);
    }

    float4* optr = reinterpret_cast<float4*>(out + ((size_t)bg * H + row) * W);
    optr[tid] = r;
}

}  // namespace

extern "C" void kernel_launch(void* const* d_in, const int* in_sizes, int n_in,
                              void* d_out, int out_size) {
    // d_in[0]: x [B,3,512,512] f32 (unused), d_in[1]: coords [B,48,3] f32
    const float* coords = (const float*)d_in[1];
    float* out = (float*)d_out;

    const int B = in_sizes[1] / (48 * 3);   // 8
    dim3 grid(H, B * 2);
    distmaps_kernel<<<grid, 128>>>(coords, out);
}